// round 4
// baseline (speedup 1.0000x reference)
#include <cuda_runtime.h>

// Trilinear resize [4,128,128,128,2] -> [4,192,192,192,2], zoom 1.5/axis.
// 3x3 (j,k) tile per thread. w=2m+2 corner obtained by warp shuffle of the
// neighbor lane's d-interpolated value (bit-exact), eliminating 6 LDG.64.
// Direct strided STG.64 (same L1 wf cost as smem staging, fewer instructions).

#define IN_S   128
#define OUT_S  192

static constexpr float INV15 = 1.0f / 1.5f;

__device__ __forceinline__ void axis_w(int o, int& i0, int& i1, float& w0, float& w1) {
    float loc = (float)o * INV15;
    float cl  = fminf(loc, 127.0f);
    int f = (int)loc;
    i0 = (f < 127) ? f : 127;
    i1 = (i0 < 127) ? (i0 + 1) : 127;
    w0 = (float)i1 - cl;
    w1 = 1.0f - w0;
}

__device__ __forceinline__ float2 lerp2(float w0, float2 a, float w1, float2 b) {
    return make_float2(w0 * a.x + w1 * b.x, w0 * a.y + w1 * b.y);
}

__global__ void __launch_bounds__(256)
resize_shfl_kernel(const float4* __restrict__ in4,
                   const float2* __restrict__ in2,
                   float2* __restrict__ out2) {
    const int lane = threadIdx.x;            // 0..31, contiguous m within warp
    const int ty   = threadIdx.y;            // 0..7
    const int half = ty & 1;                 // m half: 0 -> m in [0,32), 1 -> [32,64)
    const int nsub = ty >> 1;                // j-period sub-index 0..3
    const int m    = half * 32 + lane;       // k-period
    const int n    = blockIdx.x * 4 + nsub;  // j-period
    const int i    = blockIdx.y;
    const int b    = blockIdx.z;

    // ---- d weights ----
    int d0, d1; float wd0, wd1;
    axis_w(i, d0, d1, wd0, wd1);

    // ---- h rows + j weights ----
    const int h0r = 2 * n;
    const int h1r = 2 * n + 1;
    const int h2r = min(2 * n + 2, 127);
    float loc1 = (float)(3 * n + 1) * INV15;
    float wj1_0 = (float)(2 * n + 1) - loc1;
    float wj1_1 = 1.0f - wj1_0;
    float loc2 = fminf((float)(3 * n + 2) * INV15, 127.0f);
    float wj2_0 = (float)h2r - loc2;
    float wj2_1 = 1.0f - wj2_0;

    // ---- k phase weights ----
    float loca = (float)(3 * m + 1) * INV15;
    float wk1_0 = (float)(2 * m + 1) - loca;
    float wk1_1 = 1.0f - wk1_0;
    int   w2   = min(2 * m + 2, 127);
    float locb = fminf((float)(3 * m + 2) * INV15, 127.0f);
    float wk2_0 = (float)w2 - locb;
    float wk2_1 = 1.0f - wk2_0;

    // ---- gather: 6 x LDG.128 (w = 2m, 2m+1 for 2 channels) ----
    const float4* p4 = in4 + (size_t)b * (IN_S * IN_S * (IN_S / 2));

    int rA0 = (d0 * IN_S + h0r) * (IN_S / 2);
    int rA1 = (d0 * IN_S + h1r) * (IN_S / 2);
    int rA2 = (d0 * IN_S + h2r) * (IN_S / 2);
    int rB0 = (d1 * IN_S + h0r) * (IN_S / 2);
    int rB1 = (d1 * IN_S + h1r) * (IN_S / 2);
    int rB2 = (d1 * IN_S + h2r) * (IN_S / 2);

    float4 A0 = __ldg(p4 + rA0 + m);
    float4 A1 = __ldg(p4 + rA1 + m);
    float4 A2 = __ldg(p4 + rA2 + m);
    float4 C0 = __ldg(p4 + rB0 + m);
    float4 C1 = __ldg(p4 + rB1 + m);
    float4 C2 = __ldg(p4 + rB2 + m);

    // ---- d-interp at w=2m (t?0) and w=2m+1 (t?1), per h-row ----
    float2 t00 = lerp2(wd0, make_float2(A0.x, A0.y), wd1, make_float2(C0.x, C0.y));
    float2 t01 = lerp2(wd0, make_float2(A0.z, A0.w), wd1, make_float2(C0.z, C0.w));
    float2 t10 = lerp2(wd0, make_float2(A1.x, A1.y), wd1, make_float2(C1.x, C1.y));
    float2 t11 = lerp2(wd0, make_float2(A1.z, A1.w), wd1, make_float2(C1.z, C1.w));
    float2 t20 = lerp2(wd0, make_float2(A2.x, A2.y), wd1, make_float2(C2.x, C2.y));
    float2 t21 = lerp2(wd0, make_float2(A2.z, A2.w), wd1, make_float2(C2.z, C2.w));

    // ---- w=2m+2 corner (t?2) = neighbor lane's t?0 (bit-exact) ----
    float2 t02, t12, t22;
    t02.x = __shfl_down_sync(0xffffffffu, t00.x, 1);
    t02.y = __shfl_down_sync(0xffffffffu, t00.y, 1);
    t12.x = __shfl_down_sync(0xffffffffu, t10.x, 1);
    t12.y = __shfl_down_sync(0xffffffffu, t10.y, 1);
    t22.x = __shfl_down_sync(0xffffffffu, t20.x, 1);
    t22.y = __shfl_down_sync(0xffffffffu, t20.y, 1);

    if (lane == 31) {
        if (half == 1) {
            // m=63: w2 clipped to 127 = own t?1
            t02 = t01; t12 = t11; t22 = t21;
        } else {
            // m=31: w2 = 64, load the 6 boundary float2 and d-interp
            const float2* p2 = in2 + (size_t)b * (IN_S * IN_S * IN_S);
            float2 E0 = __ldg(p2 + rA0 * 2 + 64);
            float2 E1 = __ldg(p2 + rA1 * 2 + 64);
            float2 E2 = __ldg(p2 + rA2 * 2 + 64);
            float2 F0 = __ldg(p2 + rB0 * 2 + 64);
            float2 F1 = __ldg(p2 + rB1 * 2 + 64);
            float2 F2 = __ldg(p2 + rB2 * 2 + 64);
            t02 = lerp2(wd0, E0, wd1, F0);
            t12 = lerp2(wd0, E1, wd1, F1);
            t22 = lerp2(wd0, E2, wd1, F2);
        }
    }

    // ---- per output j-row: h-interp then k-interp, direct stores ----
    float2* orow = out2 + (((size_t)b * OUT_S + i) * OUT_S + 3 * n) * OUT_S + 3 * m;

    // j = 3n (h weight exactly {1,0}: u = t0?)
    orow[0] = t00;
    orow[1] = lerp2(wk1_0, t00, wk1_1, t01);
    orow[2] = lerp2(wk2_0, t01, wk2_1, t02);

    {   // j = 3n+1
        float2 u0 = lerp2(wj1_0, t00, wj1_1, t10);
        float2 u1 = lerp2(wj1_0, t01, wj1_1, t11);
        float2 u2 = lerp2(wj1_0, t02, wj1_1, t12);
        float2* o = orow + OUT_S;
        o[0] = u0;
        o[1] = lerp2(wk1_0, u0, wk1_1, u1);
        o[2] = lerp2(wk2_0, u1, wk2_1, u2);
    }
    {   // j = 3n+2
        float2 u0 = lerp2(wj2_0, t10, wj2_1, t20);
        float2 u1 = lerp2(wj2_0, t11, wj2_1, t21);
        float2 u2 = lerp2(wj2_0, t12, wj2_1, t22);
        float2* o = orow + 2 * OUT_S;
        o[0] = u0;
        o[1] = lerp2(wk1_0, u0, wk1_1, u1);
        o[2] = lerp2(wk2_0, u1, wk2_1, u2);
    }
}

extern "C" void kernel_launch(void* const* d_in, const int* in_sizes, int n_in,
                              void* d_out, int out_size) {
    const float4* in4 = (const float4*)d_in[0];
    const float2* in2 = (const float2*)d_in[0];
    float2*       out = (float2*)d_out;
    dim3 block(32, 8);                  // 256 threads: warp = 32 contiguous m
    dim3 grid(OUT_S / 12, OUT_S, 4);    // (16, 192, 4) — 4 j-periods x 2 halves per block
    resize_shfl_kernel<<<grid, block>>>(in4, in2, out);
}

// round 5
// speedup vs baseline: 1.5578x; 1.5578x over previous
#include <cuda_runtime.h>

// Trilinear resize [4,128,128,128,2] -> [4,192,192,192,2], zoom 1.5/axis.
// 3x3 (j,k) tile per thread. Gather: 6 LDG.128 only; the w=2m+2 corner comes
// from a warp shuffle of the neighbor lane's d-interpolated value (bit-exact).
// Stores: staged per-warp in smem, emitted as fully coalesced STG.128
// (full 32B sectors -> efficient L2/DRAM write path; direct strided STG.64
// regressed to L2=70% in R4).

#define IN_S   128
#define OUT_S  192

static constexpr float INV15 = 1.0f / 1.5f;

__device__ __forceinline__ void axis_w(int o, int& i0, int& i1, float& w0, float& w1) {
    float loc = (float)o * INV15;
    float cl  = fminf(loc, 127.0f);
    int f = (int)loc;
    i0 = (f < 127) ? f : 127;
    i1 = (i0 < 127) ? (i0 + 1) : 127;
    w0 = (float)i1 - cl;
    w1 = 1.0f - w0;
}

__device__ __forceinline__ float2 lerp2(float w0, float2 a, float w1, float2 b) {
    return make_float2(w0 * a.x + w1 * b.x, w0 * a.y + w1 * b.y);
}

__global__ void __launch_bounds__(256)
resize_shfl_staged_kernel(const float4* __restrict__ in4,
                          const float2* __restrict__ in2,
                          float4* __restrict__ out4) {
    __shared__ float sbuf[8][3][192];        // 8 warps x 3 j-rows x 768B = 18KB

    const int lane = threadIdx.x;            // 0..31 (contiguous m within warp)
    const int ty   = threadIdx.y;            // 0..7 (warp id)
    const int half = ty & 1;                 // k half: m in [0,32) or [32,64)
    const int nsub = ty >> 1;                // j-period sub-index 0..3
    const int m    = half * 32 + lane;       // k-period
    const int n    = blockIdx.x * 4 + nsub;  // j-period
    const int i    = blockIdx.y;
    const int b    = blockIdx.z;

    // ---- d weights (warp-uniform) ----
    int d0, d1; float wd0, wd1;
    axis_w(i, d0, d1, wd0, wd1);

    // ---- h rows + j weights (warp-uniform) ----
    const int h0r = 2 * n;
    const int h1r = 2 * n + 1;
    const int h2r = min(2 * n + 2, 127);
    float loc1 = (float)(3 * n + 1) * INV15;
    float wj1_0 = (float)(2 * n + 1) - loc1;
    float wj1_1 = 1.0f - wj1_0;
    float loc2 = fminf((float)(3 * n + 2) * INV15, 127.0f);
    float wj2_0 = (float)h2r - loc2;
    float wj2_1 = 1.0f - wj2_0;

    // ---- k phase weights (per lane) ----
    float loca = (float)(3 * m + 1) * INV15;
    float wk1_0 = (float)(2 * m + 1) - loca;
    float wk1_1 = 1.0f - wk1_0;
    int   w2   = min(2 * m + 2, 127);
    float locb = fminf((float)(3 * m + 2) * INV15, 127.0f);
    float wk2_0 = (float)w2 - locb;
    float wk2_1 = 1.0f - wk2_0;

    // ---- gather: 6 x LDG.128 (w = 2m and 2m+1, both channels) ----
    const float4* p4 = in4 + (size_t)b * (IN_S * IN_S * (IN_S / 2));

    int rA0 = (d0 * IN_S + h0r) * (IN_S / 2);
    int rA1 = (d0 * IN_S + h1r) * (IN_S / 2);
    int rA2 = (d0 * IN_S + h2r) * (IN_S / 2);
    int rB0 = (d1 * IN_S + h0r) * (IN_S / 2);
    int rB1 = (d1 * IN_S + h1r) * (IN_S / 2);
    int rB2 = (d1 * IN_S + h2r) * (IN_S / 2);

    float4 A0 = __ldg(p4 + rA0 + m);
    float4 A1 = __ldg(p4 + rA1 + m);
    float4 A2 = __ldg(p4 + rA2 + m);
    float4 C0 = __ldg(p4 + rB0 + m);
    float4 C1 = __ldg(p4 + rB1 + m);
    float4 C2 = __ldg(p4 + rB2 + m);

    // ---- d-interp at w=2m (t?0) and w=2m+1 (t?1) per h-row ----
    float2 t00 = lerp2(wd0, make_float2(A0.x, A0.y), wd1, make_float2(C0.x, C0.y));
    float2 t01 = lerp2(wd0, make_float2(A0.z, A0.w), wd1, make_float2(C0.z, C0.w));
    float2 t10 = lerp2(wd0, make_float2(A1.x, A1.y), wd1, make_float2(C1.x, C1.y));
    float2 t11 = lerp2(wd0, make_float2(A1.z, A1.w), wd1, make_float2(C1.z, C1.w));
    float2 t20 = lerp2(wd0, make_float2(A2.x, A2.y), wd1, make_float2(C2.x, C2.y));
    float2 t21 = lerp2(wd0, make_float2(A2.z, A2.w), wd1, make_float2(C2.z, C2.w));

    // ---- w=2m+2 corner (t?2) = next lane's t?0 (bit-exact) ----
    float2 t02, t12, t22;
    t02.x = __shfl_down_sync(0xffffffffu, t00.x, 1);
    t02.y = __shfl_down_sync(0xffffffffu, t00.y, 1);
    t12.x = __shfl_down_sync(0xffffffffu, t10.x, 1);
    t12.y = __shfl_down_sync(0xffffffffu, t10.y, 1);
    t22.x = __shfl_down_sync(0xffffffffu, t20.x, 1);
    t22.y = __shfl_down_sync(0xffffffffu, t20.y, 1);

    if (lane == 31) {
        if (half == 1) {
            // m=63: w2 clipped to 127 = own t?1
            t02 = t01; t12 = t11; t22 = t21;
        } else {
            // m=31: w2 = 64 -> load 6 boundary float2 and d-interp
            const float2* p2 = in2 + (size_t)b * (IN_S * IN_S * IN_S);
            float2 E0 = __ldg(p2 + rA0 * 2 + 64);
            float2 E1 = __ldg(p2 + rA1 * 2 + 64);
            float2 E2 = __ldg(p2 + rA2 * 2 + 64);
            float2 F0 = __ldg(p2 + rB0 * 2 + 64);
            float2 F1 = __ldg(p2 + rB1 * 2 + 64);
            float2 F2 = __ldg(p2 + rB2 * 2 + 64);
            t02 = lerp2(wd0, E0, wd1, F0);
            t12 = lerp2(wd0, E1, wd1, F1);
            t22 = lerp2(wd0, E2, wd1, F2);
        }
    }

    // ---- per output j-row: h-interp then k-interp, stage to smem ----
    {
        float2* s = (float2*)sbuf[ty][0];                  // j = 3n (h w = {1,0})
        s[lane * 3 + 0] = t00;
        s[lane * 3 + 1] = lerp2(wk1_0, t00, wk1_1, t01);
        s[lane * 3 + 2] = lerp2(wk2_0, t01, wk2_1, t02);
    }
    {
        float2 u0 = lerp2(wj1_0, t00, wj1_1, t10);
        float2 u1 = lerp2(wj1_0, t01, wj1_1, t11);
        float2 u2 = lerp2(wj1_0, t02, wj1_1, t12);
        float2* s = (float2*)sbuf[ty][1];                  // j = 3n+1
        s[lane * 3 + 0] = u0;
        s[lane * 3 + 1] = lerp2(wk1_0, u0, wk1_1, u1);
        s[lane * 3 + 2] = lerp2(wk2_0, u1, wk2_1, u2);
    }
    {
        float2 u0 = lerp2(wj2_0, t10, wj2_1, t20);
        float2 u1 = lerp2(wj2_0, t11, wj2_1, t21);
        float2 u2 = lerp2(wj2_0, t12, wj2_1, t22);
        float2* s = (float2*)sbuf[ty][2];                  // j = 3n+2
        s[lane * 3 + 0] = u0;
        s[lane * 3 + 1] = lerp2(wk1_0, u0, wk1_1, u1);
        s[lane * 3 + 2] = lerp2(wk2_0, u1, wk2_1, u2);
    }
    __syncwarp();

    // ---- coalesced STG.128: 3 rows x 48 float4 per warp ----
    #pragma unroll
    for (int r = 0; r < 3; r++) {
        const float4* s4 = (const float4*)sbuf[ty][r];
        int jrow = 3 * n + r;
        int base4 = ((b * OUT_S + i) * OUT_S + jrow) * (OUT_S / 2) + half * 48;
        out4[base4 + lane] = s4[lane];
        if (lane < 16) out4[base4 + 32 + lane] = s4[32 + lane];
    }
}

extern "C" void kernel_launch(void* const* d_in, const int* in_sizes, int n_in,
                              void* d_out, int out_size) {
    const float4* in4 = (const float4*)d_in[0];
    const float2* in2 = (const float2*)d_in[0];
    float4*       out = (float4*)d_out;
    dim3 block(32, 8);                  // 256 threads: 8 warps (4 j-periods x 2 k-halves)
    dim3 grid(OUT_S / 12, OUT_S, 4);    // (16, 192, 4)
    resize_shfl_staged_kernel<<<grid, block>>>(in4, in2, out);
}

// round 6
// speedup vs baseline: 1.7673x; 1.1345x over previous
#include <cuda_runtime.h>

// Trilinear resize [4,128,128,128,2] -> [4,192,192,192,2], zoom 1.5/axis.
// 3x3x3 (i,j,k) output tile per thread: 9 LDG.128 -> 27 float2 outputs.
// d-planes {2q,2q+1,2q+2c}, h-rows {2n,2n+1,2n+2c}, w via float4 pair + shuffle.
// Stores staged per-warp in smem -> coalesced STG.128 (full 32B sectors).

#define IN_S   128
#define OUT_S  192

static constexpr float INV15 = 1.0f / 1.5f;

__device__ __forceinline__ float2 lerp2(float w0, float2 a, float w1, float2 b) {
    return make_float2(w0 * a.x + w1 * b.x, w0 * a.y + w1 * b.y);
}

__global__ void __launch_bounds__(256, 3)
resize_tile333_kernel(const float4* __restrict__ in4,
                      const float2* __restrict__ in2,
                      float4* __restrict__ out4) {
    __shared__ float sbuf[8][3][192];        // 8 warps x 3 j-rows x 768B = 18KB

    const int lane = threadIdx.x;            // 0..31
    const int ty   = threadIdx.y;            // 0..7 (warp id)
    const int half = ty & 1;                 // k half
    const int nsub = ty >> 1;                // j-period sub-index 0..3
    const int m    = half * 32 + lane;       // k-period 0..63
    const int n    = blockIdx.x * 4 + nsub;  // j-period 0..63
    const int q    = blockIdx.y;             // i-period 0..63
    const int b    = blockIdx.z;

    // ---- i weights (warp-uniform): planes p0=2q, p1=2q+1, p2=min(2q+2,127)
    const int p2c = min(2 * q + 2, 127);
    float li1 = (float)(3 * q + 1) * INV15;
    float wi1_0 = (float)(2 * q + 1) - li1;
    float wi1_1 = 1.0f - wi1_0;
    float li2 = fminf((float)(3 * q + 2) * INV15, 127.0f);
    float wi2_0 = (float)p2c - li2;
    float wi2_1 = 1.0f - wi2_0;

    // ---- j weights (warp-uniform): rows h0=2n, h1=2n+1, h2=min(2n+2,127)
    const int h2c = min(2 * n + 2, 127);
    float lj1 = (float)(3 * n + 1) * INV15;
    float wj1_0 = (float)(2 * n + 1) - lj1;
    float wj1_1 = 1.0f - wj1_0;
    float lj2 = fminf((float)(3 * n + 2) * INV15, 127.0f);
    float wj2_0 = (float)h2c - lj2;
    float wj2_1 = 1.0f - wj2_0;

    // ---- k weights (per lane)
    float lka = (float)(3 * m + 1) * INV15;
    float wk1_0 = (float)(2 * m + 1) - lka;
    float wk1_1 = 1.0f - wk1_0;
    int   w2c  = min(2 * m + 2, 127);
    float lkb = fminf((float)(3 * m + 2) * INV15, 127.0f);
    float wk2_0 = (float)w2c - lkb;
    float wk2_1 = 1.0f - wk2_0;

    // ---- gather: 9 x LDG.128 (3 planes x 3 h-rows), w = 2m & 2m+1
    const float4* p4 = in4 + (size_t)b * (IN_S * IN_S * (IN_S / 2));
    const int pl0 = 2 * q, pl1 = 2 * q + 1;
    const int hr0 = 2 * n, hr1 = 2 * n + 1;

    int r00 = (pl0 * IN_S + hr0) * (IN_S / 2);
    int r01 = (pl0 * IN_S + hr1) * (IN_S / 2);
    int r02 = (pl0 * IN_S + h2c) * (IN_S / 2);
    int r10 = (pl1 * IN_S + hr0) * (IN_S / 2);
    int r11 = (pl1 * IN_S + hr1) * (IN_S / 2);
    int r12 = (pl1 * IN_S + h2c) * (IN_S / 2);
    int r20 = (p2c * IN_S + hr0) * (IN_S / 2);
    int r21 = (p2c * IN_S + hr1) * (IN_S / 2);
    int r22 = (p2c * IN_S + h2c) * (IN_S / 2);

    float4 P00 = __ldg(p4 + r00 + m);
    float4 P01 = __ldg(p4 + r01 + m);
    float4 P02 = __ldg(p4 + r02 + m);
    float4 P10 = __ldg(p4 + r10 + m);
    float4 P11 = __ldg(p4 + r11 + m);
    float4 P12 = __ldg(p4 + r12 + m);
    float4 P20 = __ldg(p4 + r20 + m);
    float4 P21 = __ldg(p4 + r21 + m);
    float4 P22 = __ldg(p4 + r22 + m);

    // ---- boundary raw values at w=64 (only lane31 of half 0 uses them)
    float2 B00, B01, B02, B10, B11, B12, B20, B21, B22;
    const bool bnd = (lane == 31) && (half == 0);
    if (bnd) {
        const float2* p2p = in2 + (size_t)b * (IN_S * IN_S * IN_S);
        B00 = __ldg(p2p + r00 * 2 + 64);
        B01 = __ldg(p2p + r01 * 2 + 64);
        B02 = __ldg(p2p + r02 * 2 + 64);
        B10 = __ldg(p2p + r10 * 2 + 64);
        B11 = __ldg(p2p + r11 * 2 + 64);
        B12 = __ldg(p2p + r12 * 2 + 64);
        B20 = __ldg(p2p + r20 * 2 + 64);
        B21 = __ldg(p2p + r21 * 2 + 64);
        B22 = __ldg(p2p + r22 * 2 + 64);
    }

    const int obase = (b * OUT_S + 3 * q) * OUT_S + 3 * n;   // (i,j) row origin

    #pragma unroll
    for (int ir = 0; ir < 3; ir++) {
        // ---- d-interp: t[h-row][wpos0/1] + boundary tb[h-row]
        float2 t00_, t01_, t10_, t11_, t20_, t21_;
        float2 tb0, tb1, tb2;
        if (ir == 0) {
            t00_ = make_float2(P00.x, P00.y); t01_ = make_float2(P00.z, P00.w);
            t10_ = make_float2(P01.x, P01.y); t11_ = make_float2(P01.z, P01.w);
            t20_ = make_float2(P02.x, P02.y); t21_ = make_float2(P02.z, P02.w);
            if (bnd) { tb0 = B00; tb1 = B01; tb2 = B02; }
        } else if (ir == 1) {
            t00_ = lerp2(wi1_0, make_float2(P00.x,P00.y), wi1_1, make_float2(P10.x,P10.y));
            t01_ = lerp2(wi1_0, make_float2(P00.z,P00.w), wi1_1, make_float2(P10.z,P10.w));
            t10_ = lerp2(wi1_0, make_float2(P01.x,P01.y), wi1_1, make_float2(P11.x,P11.y));
            t11_ = lerp2(wi1_0, make_float2(P01.z,P01.w), wi1_1, make_float2(P11.z,P11.w));
            t20_ = lerp2(wi1_0, make_float2(P02.x,P02.y), wi1_1, make_float2(P12.x,P12.y));
            t21_ = lerp2(wi1_0, make_float2(P02.z,P02.w), wi1_1, make_float2(P12.z,P12.w));
            if (bnd) {
                tb0 = lerp2(wi1_0, B00, wi1_1, B10);
                tb1 = lerp2(wi1_0, B01, wi1_1, B11);
                tb2 = lerp2(wi1_0, B02, wi1_1, B12);
            }
        } else {
            t00_ = lerp2(wi2_0, make_float2(P10.x,P10.y), wi2_1, make_float2(P20.x,P20.y));
            t01_ = lerp2(wi2_0, make_float2(P10.z,P10.w), wi2_1, make_float2(P20.z,P20.w));
            t10_ = lerp2(wi2_0, make_float2(P11.x,P11.y), wi2_1, make_float2(P21.x,P21.y));
            t11_ = lerp2(wi2_0, make_float2(P11.z,P11.w), wi2_1, make_float2(P21.z,P21.w));
            t20_ = lerp2(wi2_0, make_float2(P12.x,P12.y), wi2_1, make_float2(P22.x,P22.y));
            t21_ = lerp2(wi2_0, make_float2(P12.z,P12.w), wi2_1, make_float2(P22.z,P22.w));
            if (bnd) {
                tb0 = lerp2(wi2_0, B10, wi2_1, B20);
                tb1 = lerp2(wi2_0, B11, wi2_1, B21);
                tb2 = lerp2(wi2_0, B12, wi2_1, B22);
            }
        }

        // ---- h-interp per j-row, then k-interp; stage to smem
        #pragma unroll
        for (int jr = 0; jr < 3; jr++) {
            float2 u0, u1, ub;
            if (jr == 0)      { u0 = t00_; u1 = t01_; ub = tb0; }
            else if (jr == 1) {
                u0 = lerp2(wj1_0, t00_, wj1_1, t10_);
                u1 = lerp2(wj1_0, t01_, wj1_1, t11_);
                ub = lerp2(wj1_0, tb0,  wj1_1, tb1);
            } else {
                u0 = lerp2(wj2_0, t10_, wj2_1, t20_);
                u1 = lerp2(wj2_0, t11_, wj2_1, t21_);
                ub = lerp2(wj2_0, tb1,  wj2_1, tb2);
            }
            float2 u2;
            u2.x = __shfl_down_sync(0xffffffffu, u0.x, 1);
            u2.y = __shfl_down_sync(0xffffffffu, u0.y, 1);
            if (lane == 31) u2 = (half == 1) ? u1 : ub;

            float2* s = (float2*)sbuf[ty][jr];
            s[lane * 3 + 0] = u0;
            s[lane * 3 + 1] = lerp2(wk1_0, u0, wk1_1, u1);
            s[lane * 3 + 2] = lerp2(wk2_0, u1, wk2_1, u2);
        }
        __syncwarp();

        // ---- coalesced STG.128: 3 j-rows x 48 float4 per warp
        #pragma unroll
        for (int jr = 0; jr < 3; jr++) {
            const float4* s4 = (const float4*)sbuf[ty][jr];
            int base4 = (obase + ir * OUT_S + jr) * (OUT_S / 2) + half * 48;
            out4[base4 + lane] = s4[lane];
            if (lane < 16) out4[base4 + 32 + lane] = s4[32 + lane];
        }
        __syncwarp();
    }
}

extern "C" void kernel_launch(void* const* d_in, const int* in_sizes, int n_in,
                              void* d_out, int out_size) {
    const float4* in4 = (const float4*)d_in[0];
    const float2* in2 = (const float2*)d_in[0];
    float4*       out = (float4*)d_out;
    dim3 block(32, 8);                  // 256 threads
    dim3 grid(OUT_S / 12, OUT_S / 3, 4); // (16, 64, 4) = 4096 blocks
    resize_tile333_kernel<<<grid, block>>>(in4, in2, out);
}